// round 1
// baseline (speedup 1.0000x reference)
#include <cuda_runtime.h>

#define N_NODES 100000
#define N_FEAT  256
#define OUT_DIM 128
#define NNZ_X   1600000
#define NNZ_A   1600000

// Scratch: xw = X @ W, [N_NODES, OUT_DIM] fp32 = 51.2 MB (fits in L2).
__device__ float g_xw[(size_t)N_NODES * OUT_DIM];

// ---------------------------------------------------------------------------
// Zero xw scratch and the output buffer (d_out is poisoned by the harness).
// ---------------------------------------------------------------------------
__global__ void zero_kernel(float* __restrict__ out) {
    const size_t n4 = (size_t)N_NODES * OUT_DIM / 4;  // 3.2M float4s
    float4 z = make_float4(0.f, 0.f, 0.f, 0.f);
    float4* xw4  = reinterpret_cast<float4*>(g_xw);
    float4* out4 = reinterpret_cast<float4*>(out);
    for (size_t i = (size_t)blockIdx.x * blockDim.x + threadIdx.x; i < n4;
         i += (size_t)gridDim.x * blockDim.x) {
        xw4[i]  = z;
        out4[i] = z;
    }
}

// ---------------------------------------------------------------------------
// Stage 1: xw[feat_rows[i], :] += feat_vals[i] * W[feat_cols[i], :]
// One warp per nonzero; each lane handles 4 contiguous output dims (float4).
// W row = 128 floats = 32 float4s -> lane l reads W4[c*32 + l].
// ---------------------------------------------------------------------------
__global__ void scatter_xw_kernel(const int* __restrict__ rows,
                                  const int* __restrict__ cols,
                                  const float* __restrict__ vals,
                                  const float* __restrict__ W) {
    int gtid = blockIdx.x * blockDim.x + threadIdx.x;
    int nz   = gtid >> 5;
    int lane = gtid & 31;
    if (nz >= NNZ_X) return;

    int   r = __ldg(rows + nz);
    int   c = __ldg(cols + nz);
    float v = __ldg(vals + nz);

    const float4* W4 = reinterpret_cast<const float4*>(W);
    float4 w = __ldg(W4 + (size_t)c * 32 + lane);
    float4 a = make_float4(v * w.x, v * w.y, v * w.z, v * w.w);

    float4* dst = reinterpret_cast<float4*>(g_xw + (size_t)r * OUT_DIM) + lane;
    atomicAdd(dst, a);   // sm_90+: RED.E.ADD.F32x4
}

// ---------------------------------------------------------------------------
// Stage 2: out[adj_rows[e], :] += adj_vals[e] * xw[adj_cols[e], :]
// One warp per edge; gather 512B row from g_xw (L2-resident), vector-atomic
// into out.
// ---------------------------------------------------------------------------
__global__ void scatter_agg_kernel(const int* __restrict__ rows,
                                   const int* __restrict__ cols,
                                   const float* __restrict__ vals,
                                   float* __restrict__ out) {
    int gtid = blockIdx.x * blockDim.x + threadIdx.x;
    int e    = gtid >> 5;
    int lane = gtid & 31;
    if (e >= NNZ_A) return;

    int   dst = __ldg(rows + e);
    int   src = __ldg(cols + e);
    float v   = __ldg(vals + e);

    const float4* src4 = reinterpret_cast<const float4*>(g_xw + (size_t)src * OUT_DIM) + lane;
    float4 x = __ldg(src4);
    float4 a = make_float4(v * x.x, v * x.y, v * x.z, v * x.w);

    float4* d = reinterpret_cast<float4*>(out + (size_t)dst * OUT_DIM) + lane;
    atomicAdd(d, a);
}

// ---------------------------------------------------------------------------
// Final ReLU in place on out.
// ---------------------------------------------------------------------------
__global__ void relu_kernel(float* __restrict__ out) {
    const size_t n4 = (size_t)N_NODES * OUT_DIM / 4;
    float4* out4 = reinterpret_cast<float4*>(out);
    for (size_t i = (size_t)blockIdx.x * blockDim.x + threadIdx.x; i < n4;
         i += (size_t)gridDim.x * blockDim.x) {
        float4 x = out4[i];
        x.x = fmaxf(x.x, 0.f);
        x.y = fmaxf(x.y, 0.f);
        x.z = fmaxf(x.z, 0.f);
        x.w = fmaxf(x.w, 0.f);
        out4[i] = x;
    }
}

// ---------------------------------------------------------------------------
// metadata order: feat_rows, feat_cols, feat_vals, adj_rows, adj_cols,
//                 adj_vals, W, n_nodes
// ---------------------------------------------------------------------------
extern "C" void kernel_launch(void* const* d_in, const int* in_sizes, int n_in,
                              void* d_out, int out_size) {
    const int*   feat_rows = (const int*)d_in[0];
    const int*   feat_cols = (const int*)d_in[1];
    const float* feat_vals = (const float*)d_in[2];
    const int*   adj_rows  = (const int*)d_in[3];
    const int*   adj_cols  = (const int*)d_in[4];
    const float* adj_vals  = (const float*)d_in[5];
    const float* W         = (const float*)d_in[6];
    float* out = (float*)d_out;

    // Zero scratch + output
    zero_kernel<<<2048, 256>>>(out);

    // Stage 1: warp per nnz, 8 warps per 256-thread block
    int blocks1 = (NNZ_X * 32 + 255) / 256;
    scatter_xw_kernel<<<blocks1, 256>>>(feat_rows, feat_cols, feat_vals, W);

    // Stage 2
    int blocks2 = (NNZ_A * 32 + 255) / 256;
    scatter_agg_kernel<<<blocks2, 256>>>(adj_rows, adj_cols, adj_vals, out);

    // ReLU
    relu_kernel<<<2048, 256>>>(out);
}

// round 3
// speedup vs baseline: 2.0432x; 2.0432x over previous
#include <cuda_runtime.h>

#define N_NODES 100000
#define N_FEAT  256
#define OUT_DIM 128
#define NNZ_X   1600000
#define NNZ_A   1600000

#define SCAN_CHUNK 2048          // 256 threads x 8 elems
#define SCAN_NBLK  ((N_NODES + SCAN_CHUNK - 1) / SCAN_CHUNK)   // 49

// ---------------- device scratch (no allocations allowed) ----------------
// NOTE: these are only ever referenced from DEVICE code. Passing a __device__
// global as a kernel argument from host code passes the host shadow symbol
// (garbage) — that was the round-2 bug.
__device__ float g_xw[(size_t)N_NODES * OUT_DIM];   // 51.2 MB, L2-resident

__device__ int   g_cnt_f[N_NODES];
__device__ int   g_cnt_a[N_NODES];
__device__ int   g_off_f[N_NODES];
__device__ int   g_off_a[N_NODES];
__device__ int   g_cur_f[N_NODES];   // scatter cursor; after scatter = segment end
__device__ int   g_cur_a[N_NODES];
__device__ int   g_bsum_f[SCAN_NBLK];
__device__ int   g_bsum_a[SCAN_NBLK];

__device__ int   g_scol_f[NNZ_X];
__device__ float g_sval_f[NNZ_X];
__device__ int   g_scol_a[NNZ_A];
__device__ float g_sval_a[NNZ_A];

// ---------------------------------------------------------------------------
// 0) zero both histograms
// ---------------------------------------------------------------------------
__global__ void zero_cnt_kernel() {
    int i = blockIdx.x * blockDim.x + threadIdx.x;
    if (i < N_NODES) { g_cnt_f[i] = 0; g_cnt_a[i] = 0; }
}

// ---------------------------------------------------------------------------
// 1) histogram both row arrays (fused)
// ---------------------------------------------------------------------------
__global__ void hist_kernel(const int* __restrict__ rows_f,
                            const int* __restrict__ rows_a) {
    int i = blockIdx.x * blockDim.x + threadIdx.x;
    if (i < NNZ_X) atomicAdd(&g_cnt_f[__ldg(rows_f + i)], 1);
    if (i < NNZ_A) atomicAdd(&g_cnt_a[__ldg(rows_a + i)], 1);
}

// ---------------------------------------------------------------------------
// 2) per-chunk partial sums (gridDim.y = 2 selects feat/adj)
// ---------------------------------------------------------------------------
__global__ void block_sum_kernel() {
    __shared__ int s[256];
    const int* cnt = (blockIdx.y == 0) ? g_cnt_f : g_cnt_a;
    int*      bsum = (blockIdx.y == 0) ? g_bsum_f : g_bsum_a;
    int t = threadIdx.x;
    int base = blockIdx.x * SCAN_CHUNK + t * 8;
    int sum = 0;
#pragma unroll
    for (int k = 0; k < 8; k++) {
        int idx = base + k;
        if (idx < N_NODES) sum += cnt[idx];
    }
    s[t] = sum;
    __syncthreads();
    for (int d = 128; d > 0; d >>= 1) {
        if (t < d) s[t] += s[t + d];
        __syncthreads();
    }
    if (t == 0) bsum[blockIdx.x] = s[0];
}

// ---------------------------------------------------------------------------
// 3) exclusive scan of the (49-entry) block sums — serial, tiny
// ---------------------------------------------------------------------------
__global__ void scan_bsum_kernel() {
    int t = threadIdx.x;
    if (t < 2) {
        int* b = (t == 0) ? g_bsum_f : g_bsum_a;
        int acc = 0;
        for (int i = 0; i < SCAN_NBLK; i++) { int v = b[i]; b[i] = acc; acc += v; }
    }
}

// ---------------------------------------------------------------------------
// 4) per-chunk exclusive scan + add carry; write offsets and cursors
// ---------------------------------------------------------------------------
__global__ void scan_add_kernel() {
    __shared__ int s[256];
    const int* cnt;  const int* bsum;  int* off;  int* cur;
    if (blockIdx.y == 0) { cnt = g_cnt_f; bsum = g_bsum_f; off = g_off_f; cur = g_cur_f; }
    else                 { cnt = g_cnt_a; bsum = g_bsum_a; off = g_off_a; cur = g_cur_a; }

    int t = threadIdx.x;
    int base = blockIdx.x * SCAN_CHUNK + t * 8;
    int local[8];
    int sum = 0;
#pragma unroll
    for (int k = 0; k < 8; k++) {
        int idx = base + k;
        local[k] = (idx < N_NODES) ? cnt[idx] : 0;
        sum += local[k];
    }
    s[t] = sum;
    __syncthreads();
    // Hillis-Steele inclusive scan
    for (int d = 1; d < 256; d <<= 1) {
        int v = (t >= d) ? s[t - d] : 0;
        __syncthreads();
        s[t] += v;
        __syncthreads();
    }
    int excl = (t == 0) ? 0 : s[t - 1];
    int run = bsum[blockIdx.x] + excl;
#pragma unroll
    for (int k = 0; k < 8; k++) {
        int idx = base + k;
        if (idx < N_NODES) { off[idx] = run; cur[idx] = run; run += local[k]; }
    }
}

// ---------------------------------------------------------------------------
// 5) scatter (col,val) pairs into row-sorted order using atomic cursors.
//    Globals referenced in device code (NOT passed from host).
// ---------------------------------------------------------------------------
__global__ void scatter_pairs_f_kernel(const int* __restrict__ rows,
                                       const int* __restrict__ cols,
                                       const float* __restrict__ vals) {
    int i = blockIdx.x * blockDim.x + threadIdx.x;
    if (i >= NNZ_X) return;
    int r = __ldg(rows + i);
    int pos = atomicAdd(&g_cur_f[r], 1);
    g_scol_f[pos] = __ldg(cols + i);
    g_sval_f[pos] = __ldg(vals + i);
}

__global__ void scatter_pairs_a_kernel(const int* __restrict__ rows,
                                       const int* __restrict__ cols,
                                       const float* __restrict__ vals) {
    int i = blockIdx.x * blockDim.x + threadIdx.x;
    if (i >= NNZ_A) return;
    int r = __ldg(rows + i);
    int pos = atomicAdd(&g_cur_a[r], 1);
    g_scol_a[pos] = __ldg(cols + i);
    g_sval_a[pos] = __ldg(vals + i);
}

// ---------------------------------------------------------------------------
// 6) stage 1 gather: xw[r,:] = sum_j sval[j] * W[scol[j],:]
//    warp per node row; lane owns 4 contiguous dims (float4)
// ---------------------------------------------------------------------------
__global__ void xw_gather_kernel(const float* __restrict__ W) {
    int gtid = blockIdx.x * blockDim.x + threadIdx.x;
    int r    = gtid >> 5;
    int lane = gtid & 31;
    if (r >= N_NODES) return;

    int s = g_off_f[r];
    int e = g_cur_f[r];     // = off + count after scatter

    const float4* W4 = reinterpret_cast<const float4*>(W);
    float4 acc = make_float4(0.f, 0.f, 0.f, 0.f);
    for (int j = s; j < e; j++) {
        int   c = __ldg(g_scol_f + j);
        float v = __ldg(g_sval_f + j);
        float4 w = __ldg(W4 + (size_t)c * 32 + lane);
        acc.x = fmaf(v, w.x, acc.x);
        acc.y = fmaf(v, w.y, acc.y);
        acc.z = fmaf(v, w.z, acc.z);
        acc.w = fmaf(v, w.w, acc.w);
    }
    reinterpret_cast<float4*>(g_xw + (size_t)r * OUT_DIM)[lane] = acc;
}

// ---------------------------------------------------------------------------
// 7) stage 2 gather + ReLU: out[r,:] = relu(sum_j sval[j] * xw[scol[j],:])
// ---------------------------------------------------------------------------
__global__ void agg_gather_kernel(float* __restrict__ out) {
    int gtid = blockIdx.x * blockDim.x + threadIdx.x;
    int r    = gtid >> 5;
    int lane = gtid & 31;
    if (r >= N_NODES) return;

    int s = g_off_a[r];
    int e = g_cur_a[r];

    const float4* XW4 = reinterpret_cast<const float4*>(g_xw);
    float4 acc = make_float4(0.f, 0.f, 0.f, 0.f);
    for (int j = s; j < e; j++) {
        int   src = __ldg(g_scol_a + j);
        float v   = __ldg(g_sval_a + j);
        float4 x  = __ldg(XW4 + (size_t)src * 32 + lane);
        acc.x = fmaf(v, x.x, acc.x);
        acc.y = fmaf(v, x.y, acc.y);
        acc.z = fmaf(v, x.z, acc.z);
        acc.w = fmaf(v, x.w, acc.w);
    }
    acc.x = fmaxf(acc.x, 0.f);
    acc.y = fmaxf(acc.y, 0.f);
    acc.z = fmaxf(acc.z, 0.f);
    acc.w = fmaxf(acc.w, 0.f);
    reinterpret_cast<float4*>(out + (size_t)r * OUT_DIM)[lane] = acc;
}

// ---------------------------------------------------------------------------
// metadata order: feat_rows, feat_cols, feat_vals, adj_rows, adj_cols,
//                 adj_vals, W, n_nodes
// ---------------------------------------------------------------------------
extern "C" void kernel_launch(void* const* d_in, const int* in_sizes, int n_in,
                              void* d_out, int out_size) {
    const int*   feat_rows = (const int*)d_in[0];
    const int*   feat_cols = (const int*)d_in[1];
    const float* feat_vals = (const float*)d_in[2];
    const int*   adj_rows  = (const int*)d_in[3];
    const int*   adj_cols  = (const int*)d_in[4];
    const float* adj_vals  = (const float*)d_in[5];
    const float* W         = (const float*)d_in[6];
    float* out = (float*)d_out;

    // CSR build for both sparse inputs
    zero_cnt_kernel<<<(N_NODES + 255) / 256, 256>>>();
    hist_kernel<<<(NNZ_X + 255) / 256, 256>>>(feat_rows, adj_rows);

    dim3 sg(SCAN_NBLK, 2);
    block_sum_kernel<<<sg, 256>>>();
    scan_bsum_kernel<<<1, 32>>>();
    scan_add_kernel<<<sg, 256>>>();

    scatter_pairs_f_kernel<<<(NNZ_X + 255) / 256, 256>>>(feat_rows, feat_cols, feat_vals);
    scatter_pairs_a_kernel<<<(NNZ_A + 255) / 256, 256>>>(adj_rows, adj_cols, adj_vals);

    // gather-reduce stages (no atomics, single write per row)
    int blocks = (N_NODES * 32 + 255) / 256;
    xw_gather_kernel<<<blocks, 256>>>(W);
    agg_gather_kernel<<<blocks, 256>>>(out);
}

// round 4
// speedup vs baseline: 2.2700x; 1.1110x over previous
#include <cuda_runtime.h>
#include <cuda_fp16.h>

#define N_NODES 100000
#define N_FEAT  256
#define OUT_DIM 128
#define NNZ_X   1600000
#define NNZ_A   1600000

#define SCAN_CHUNK 2048          // 256 threads x 8 elems
#define SCAN_NBLK  ((N_NODES + SCAN_CHUNK - 1) / SCAN_CHUNK)   // 49

// ---------------- device scratch (device-code references only) ----------------
// xw stored as fp16, packed 4 dims per uint2 (8B): row = 32 uint2 = 256 B.
__device__ uint2 g_xw2[(size_t)N_NODES * OUT_DIM / 4];   // 25.6 MB, L2-resident

__device__ int   g_cnt_f[N_NODES];
__device__ int   g_cnt_a[N_NODES];
__device__ int   g_off_f[N_NODES];
__device__ int   g_off_a[N_NODES];
__device__ int   g_cur_f[N_NODES];   // scatter cursor; after scatter = segment end
__device__ int   g_cur_a[N_NODES];
__device__ int   g_bsum_f[SCAN_NBLK];
__device__ int   g_bsum_a[SCAN_NBLK];

__device__ int   g_scol_f[NNZ_X];
__device__ float g_sval_f[NNZ_X];
__device__ int   g_scol_a[NNZ_A];
__device__ float g_sval_a[NNZ_A];

// ---------------------------------------------------------------------------
// 0) zero both histograms
// ---------------------------------------------------------------------------
__global__ void zero_cnt_kernel() {
    int i = blockIdx.x * blockDim.x + threadIdx.x;
    if (i < N_NODES) { g_cnt_f[i] = 0; g_cnt_a[i] = 0; }
}

// ---------------------------------------------------------------------------
// 1) histogram both row arrays (fused)
// ---------------------------------------------------------------------------
__global__ void hist_kernel(const int* __restrict__ rows_f,
                            const int* __restrict__ rows_a) {
    int i = blockIdx.x * blockDim.x + threadIdx.x;
    if (i < NNZ_X) atomicAdd(&g_cnt_f[__ldg(rows_f + i)], 1);
    if (i < NNZ_A) atomicAdd(&g_cnt_a[__ldg(rows_a + i)], 1);
}

// ---------------------------------------------------------------------------
// 2) per-chunk partial sums (gridDim.y = 2 selects feat/adj)
// ---------------------------------------------------------------------------
__global__ void block_sum_kernel() {
    __shared__ int s[256];
    const int* cnt = (blockIdx.y == 0) ? g_cnt_f : g_cnt_a;
    int*      bsum = (blockIdx.y == 0) ? g_bsum_f : g_bsum_a;
    int t = threadIdx.x;
    int base = blockIdx.x * SCAN_CHUNK + t * 8;
    int sum = 0;
#pragma unroll
    for (int k = 0; k < 8; k++) {
        int idx = base + k;
        if (idx < N_NODES) sum += cnt[idx];
    }
    s[t] = sum;
    __syncthreads();
    for (int d = 128; d > 0; d >>= 1) {
        if (t < d) s[t] += s[t + d];
        __syncthreads();
    }
    if (t == 0) bsum[blockIdx.x] = s[0];
}

// ---------------------------------------------------------------------------
// 3) exclusive scan of the 49-entry block sums — warp-parallel (64 lanes/array)
//    threads [0,64) handle feat, [64,128) handle adj.
// ---------------------------------------------------------------------------
__global__ void scan_bsum_kernel() {
    __shared__ int s[2][64];
    int t   = threadIdx.x;
    int grp = t >> 6;        // 0 = feat, 1 = adj
    int i   = t & 63;
    int* b  = (grp == 0) ? g_bsum_f : g_bsum_a;
    s[grp][i] = (i < SCAN_NBLK) ? b[i] : 0;
    __syncthreads();
#pragma unroll
    for (int d = 1; d < 64; d <<= 1) {
        int v = (i >= d) ? s[grp][i - d] : 0;
        __syncthreads();
        s[grp][i] += v;
        __syncthreads();
    }
    if (i < SCAN_NBLK) b[i] = (i == 0) ? 0 : s[grp][i - 1];
}

// ---------------------------------------------------------------------------
// 4) per-chunk exclusive scan + add carry; write offsets and cursors
// ---------------------------------------------------------------------------
__global__ void scan_add_kernel() {
    __shared__ int s[256];
    const int* cnt;  const int* bsum;  int* off;  int* cur;
    if (blockIdx.y == 0) { cnt = g_cnt_f; bsum = g_bsum_f; off = g_off_f; cur = g_cur_f; }
    else                 { cnt = g_cnt_a; bsum = g_bsum_a; off = g_off_a; cur = g_cur_a; }

    int t = threadIdx.x;
    int base = blockIdx.x * SCAN_CHUNK + t * 8;
    int local[8];
    int sum = 0;
#pragma unroll
    for (int k = 0; k < 8; k++) {
        int idx = base + k;
        local[k] = (idx < N_NODES) ? cnt[idx] : 0;
        sum += local[k];
    }
    s[t] = sum;
    __syncthreads();
    for (int d = 1; d < 256; d <<= 1) {
        int v = (t >= d) ? s[t - d] : 0;
        __syncthreads();
        s[t] += v;
        __syncthreads();
    }
    int excl = (t == 0) ? 0 : s[t - 1];
    int run = bsum[blockIdx.x] + excl;
#pragma unroll
    for (int k = 0; k < 8; k++) {
        int idx = base + k;
        if (idx < N_NODES) { off[idx] = run; cur[idx] = run; run += local[k]; }
    }
}

// ---------------------------------------------------------------------------
// 5) scatter (col,val) pairs into row-sorted order using atomic cursors.
//    blockIdx.y selects feat(0)/adj(1). Globals referenced in device code.
// ---------------------------------------------------------------------------
__global__ void scatter_pairs_kernel(const int* __restrict__ rows_f,
                                     const int* __restrict__ cols_f,
                                     const float* __restrict__ vals_f,
                                     const int* __restrict__ rows_a,
                                     const int* __restrict__ cols_a,
                                     const float* __restrict__ vals_a) {
    int i = blockIdx.x * blockDim.x + threadIdx.x;
    if (blockIdx.y == 0) {
        if (i >= NNZ_X) return;
        int r = __ldg(rows_f + i);
        int pos = atomicAdd(&g_cur_f[r], 1);
        g_scol_f[pos] = __ldg(cols_f + i);
        g_sval_f[pos] = __ldg(vals_f + i);
    } else {
        if (i >= NNZ_A) return;
        int r = __ldg(rows_a + i);
        int pos = atomicAdd(&g_cur_a[r], 1);
        g_scol_a[pos] = __ldg(cols_a + i);
        g_sval_a[pos] = __ldg(vals_a + i);
    }
}

// ---------------------------------------------------------------------------
// 6) stage 1 gather: xw[r,:] = sum_j sval[j] * W[scol[j],:]
//    warp per node row; lane owns 4 contiguous dims; fp32 accumulate,
//    one fp16 round at the end.
// ---------------------------------------------------------------------------
__global__ void xw_gather_kernel(const float* __restrict__ W) {
    int gtid = blockIdx.x * blockDim.x + threadIdx.x;
    int r    = gtid >> 5;
    int lane = gtid & 31;
    if (r >= N_NODES) return;

    int s = g_off_f[r];
    int e = g_cur_f[r];

    const float4* W4 = reinterpret_cast<const float4*>(W);
    float4 acc = make_float4(0.f, 0.f, 0.f, 0.f);
    for (int j = s; j < e; j++) {
        int   c = __ldg(g_scol_f + j);
        float v = __ldg(g_sval_f + j);
        float4 w = __ldg(W4 + (size_t)c * 32 + lane);
        acc.x = fmaf(v, w.x, acc.x);
        acc.y = fmaf(v, w.y, acc.y);
        acc.z = fmaf(v, w.z, acc.z);
        acc.w = fmaf(v, w.w, acc.w);
    }
    __half2 h01 = __floats2half2_rn(acc.x, acc.y);
    __half2 h23 = __floats2half2_rn(acc.z, acc.w);
    uint2 u;
    u.x = *reinterpret_cast<unsigned*>(&h01);
    u.y = *reinterpret_cast<unsigned*>(&h23);
    g_xw2[(size_t)r * 32 + lane] = u;
}

// ---------------------------------------------------------------------------
// 7) stage 2 gather + ReLU: out[r,:] = relu(sum_j sval[j] * xw[scol[j],:])
//    xw rows are 256 B fp16 — half the L2 traffic of fp32.
// ---------------------------------------------------------------------------
__global__ void agg_gather_kernel(float* __restrict__ out) {
    int gtid = blockIdx.x * blockDim.x + threadIdx.x;
    int r    = gtid >> 5;
    int lane = gtid & 31;
    if (r >= N_NODES) return;

    int s = g_off_a[r];
    int e = g_cur_a[r];

    float4 acc = make_float4(0.f, 0.f, 0.f, 0.f);
    for (int j = s; j < e; j++) {
        int   src = __ldg(g_scol_a + j);
        float v   = __ldg(g_sval_a + j);
        uint2 u   = __ldg(g_xw2 + (size_t)src * 32 + lane);
        __half2 h01 = *reinterpret_cast<__half2*>(&u.x);
        __half2 h23 = *reinterpret_cast<__half2*>(&u.y);
        float2 f01 = __half22float2(h01);
        float2 f23 = __half22float2(h23);
        acc.x = fmaf(v, f01.x, acc.x);
        acc.y = fmaf(v, f01.y, acc.y);
        acc.z = fmaf(v, f23.x, acc.z);
        acc.w = fmaf(v, f23.y, acc.w);
    }
    acc.x = fmaxf(acc.x, 0.f);
    acc.y = fmaxf(acc.y, 0.f);
    acc.z = fmaxf(acc.z, 0.f);
    acc.w = fmaxf(acc.w, 0.f);
    reinterpret_cast<float4*>(out + (size_t)r * OUT_DIM)[lane] = acc;
}

// ---------------------------------------------------------------------------
// metadata order: feat_rows, feat_cols, feat_vals, adj_rows, adj_cols,
//                 adj_vals, W, n_nodes
// ---------------------------------------------------------------------------
extern "C" void kernel_launch(void* const* d_in, const int* in_sizes, int n_in,
                              void* d_out, int out_size) {
    const int*   feat_rows = (const int*)d_in[0];
    const int*   feat_cols = (const int*)d_in[1];
    const float* feat_vals = (const float*)d_in[2];
    const int*   adj_rows  = (const int*)d_in[3];
    const int*   adj_cols  = (const int*)d_in[4];
    const float* adj_vals  = (const float*)d_in[5];
    const float* W         = (const float*)d_in[6];
    float* out = (float*)d_out;

    zero_cnt_kernel<<<(N_NODES + 255) / 256, 256>>>();
    hist_kernel<<<(NNZ_X + 255) / 256, 256>>>(feat_rows, adj_rows);

    dim3 sg(SCAN_NBLK, 2);
    block_sum_kernel<<<sg, 256>>>();
    scan_bsum_kernel<<<1, 128>>>();
    scan_add_kernel<<<sg, 256>>>();

    dim3 sc((NNZ_X + 255) / 256, 2);
    scatter_pairs_kernel<<<sc, 256>>>(feat_rows, feat_cols, feat_vals,
                                      adj_rows, adj_cols, adj_vals);

    int blocks = (N_NODES * 32 + 255) / 256;
    xw_gather_kernel<<<blocks, 256>>>(W);
    agg_gather_kernel<<<blocks, 256>>>(out);
}

// round 5
// speedup vs baseline: 2.5202x; 1.1102x over previous
#include <cuda_runtime.h>
#include <cuda_fp16.h>

#define N_NODES 100000
#define N_FEAT  256
#define OUT_DIM 128
#define NNZ_X   1600000
#define NNZ_A   1600000

#define SCAN_CHUNK 2048          // 256 threads x 8 elems
#define SCAN_NBLK  ((N_NODES + SCAN_CHUNK - 1) / SCAN_CHUNK)   // 49

// ---------------- device scratch (device-code references only) ----------------
// xw stored as fp16: row = 128 fp16 = 256 B = 16 uint4.
__device__ uint4 g_xw4[(size_t)N_NODES * 16];     // 25.6 MB, L2-resident

__device__ int   g_cnt_f[N_NODES];
__device__ int   g_cnt_a[N_NODES];
__device__ int   g_off_f[N_NODES];
__device__ int   g_off_a[N_NODES];
__device__ int   g_cur_f[N_NODES];
__device__ int   g_cur_a[N_NODES];
__device__ int   g_bsum_f[SCAN_NBLK];
__device__ int   g_bsum_a[SCAN_NBLK];

// packed (col, val-bits) pairs, row-sorted
__device__ int2  g_pair_f[NNZ_X];
__device__ int2  g_pair_a[NNZ_A];

// ---------------------------------------------------------------------------
// 0) zero both histograms
// ---------------------------------------------------------------------------
__global__ void zero_cnt_kernel() {
    int i = blockIdx.x * blockDim.x + threadIdx.x;
    if (i < N_NODES) { g_cnt_f[i] = 0; g_cnt_a[i] = 0; }
}

// ---------------------------------------------------------------------------
// 1) histogram both row arrays (fused)
// ---------------------------------------------------------------------------
__global__ void hist_kernel(const int* __restrict__ rows_f,
                            const int* __restrict__ rows_a) {
    int i = blockIdx.x * blockDim.x + threadIdx.x;
    if (i < NNZ_X) atomicAdd(&g_cnt_f[__ldg(rows_f + i)], 1);
    if (i < NNZ_A) atomicAdd(&g_cnt_a[__ldg(rows_a + i)], 1);
}

// ---------------------------------------------------------------------------
// 2) per-chunk partial sums (gridDim.y = 2 selects feat/adj)
// ---------------------------------------------------------------------------
__global__ void block_sum_kernel() {
    __shared__ int s[256];
    const int* cnt = (blockIdx.y == 0) ? g_cnt_f : g_cnt_a;
    int*      bsum = (blockIdx.y == 0) ? g_bsum_f : g_bsum_a;
    int t = threadIdx.x;
    int base = blockIdx.x * SCAN_CHUNK + t * 8;
    int sum = 0;
#pragma unroll
    for (int k = 0; k < 8; k++) {
        int idx = base + k;
        if (idx < N_NODES) sum += cnt[idx];
    }
    s[t] = sum;
    __syncthreads();
    for (int d = 128; d > 0; d >>= 1) {
        if (t < d) s[t] += s[t + d];
        __syncthreads();
    }
    if (t == 0) bsum[blockIdx.x] = s[0];
}

// ---------------------------------------------------------------------------
// 3) exclusive scan of the 49-entry block sums (both arrays in one block)
// ---------------------------------------------------------------------------
__global__ void scan_bsum_kernel() {
    __shared__ int s[2][64];
    int t   = threadIdx.x;
    int grp = t >> 6;        // 0 = feat, 1 = adj
    int i   = t & 63;
    int* b  = (grp == 0) ? g_bsum_f : g_bsum_a;
    s[grp][i] = (i < SCAN_NBLK) ? b[i] : 0;
    __syncthreads();
#pragma unroll
    for (int d = 1; d < 64; d <<= 1) {
        int v = (i >= d) ? s[grp][i - d] : 0;
        __syncthreads();
        s[grp][i] += v;
        __syncthreads();
    }
    if (i < SCAN_NBLK) b[i] = (i == 0) ? 0 : s[grp][i - 1];
}

// ---------------------------------------------------------------------------
// 4) per-chunk exclusive scan + add carry; write offsets and cursors
// ---------------------------------------------------------------------------
__global__ void scan_add_kernel() {
    __shared__ int s[256];
    const int* cnt;  const int* bsum;  int* off;  int* cur;
    if (blockIdx.y == 0) { cnt = g_cnt_f; bsum = g_bsum_f; off = g_off_f; cur = g_cur_f; }
    else                 { cnt = g_cnt_a; bsum = g_bsum_a; off = g_off_a; cur = g_cur_a; }

    int t = threadIdx.x;
    int base = blockIdx.x * SCAN_CHUNK + t * 8;
    int local[8];
    int sum = 0;
#pragma unroll
    for (int k = 0; k < 8; k++) {
        int idx = base + k;
        local[k] = (idx < N_NODES) ? cnt[idx] : 0;
        sum += local[k];
    }
    s[t] = sum;
    __syncthreads();
    for (int d = 1; d < 256; d <<= 1) {
        int v = (t >= d) ? s[t - d] : 0;
        __syncthreads();
        s[t] += v;
        __syncthreads();
    }
    int excl = (t == 0) ? 0 : s[t - 1];
    int run = bsum[blockIdx.x] + excl;
#pragma unroll
    for (int k = 0; k < 8; k++) {
        int idx = base + k;
        if (idx < N_NODES) { off[idx] = run; cur[idx] = run; run += local[k]; }
    }
}

// ---------------------------------------------------------------------------
// 5) scatter packed (col,val) pairs into row-sorted order (atomic cursors).
//    One 8B store per nnz instead of two 4B stores — halves sector traffic.
//    blockIdx.y selects feat(0)/adj(1).
// ---------------------------------------------------------------------------
__global__ void scatter_pairs_kernel(const int* __restrict__ rows_f,
                                     const int* __restrict__ cols_f,
                                     const float* __restrict__ vals_f,
                                     const int* __restrict__ rows_a,
                                     const int* __restrict__ cols_a,
                                     const float* __restrict__ vals_a) {
    int i = blockIdx.x * blockDim.x + threadIdx.x;
    if (blockIdx.y == 0) {
        if (i >= NNZ_X) return;
        int r = __ldg(rows_f + i);
        int pos = atomicAdd(&g_cur_f[r], 1);
        int2 p;
        p.x = __ldg(cols_f + i);
        p.y = __float_as_int(__ldg(vals_f + i));
        g_pair_f[pos] = p;
    } else {
        if (i >= NNZ_A) return;
        int r = __ldg(rows_a + i);
        int pos = atomicAdd(&g_cur_a[r], 1);
        int2 p;
        p.x = __ldg(cols_a + i);
        p.y = __float_as_int(__ldg(vals_a + i));
        g_pair_a[pos] = p;
    }
}

// ---------------------------------------------------------------------------
// 6) stage 1 gather: xw[r,:] = sum_j val[j] * W[col[j],:]
//    warp per node row; lane owns 4 dims; fp32 accumulate, fp16 round once.
// ---------------------------------------------------------------------------
__global__ void xw_gather_kernel(const float* __restrict__ W) {
    int gtid = blockIdx.x * blockDim.x + threadIdx.x;
    int r    = gtid >> 5;
    int lane = gtid & 31;
    if (r >= N_NODES) return;

    int s = g_off_f[r];
    int e = g_cur_f[r];

    const float4* W4 = reinterpret_cast<const float4*>(W);
    float4 acc = make_float4(0.f, 0.f, 0.f, 0.f);
#pragma unroll 2
    for (int j = s; j < e; j++) {
        int2 p = __ldg(g_pair_f + j);
        float v = __int_as_float(p.y);
        float4 w = __ldg(W4 + (size_t)p.x * 32 + lane);
        acc.x = fmaf(v, w.x, acc.x);
        acc.y = fmaf(v, w.y, acc.y);
        acc.z = fmaf(v, w.z, acc.z);
        acc.w = fmaf(v, w.w, acc.w);
    }
    __half2 h01 = __floats2half2_rn(acc.x, acc.y);
    __half2 h23 = __floats2half2_rn(acc.z, acc.w);
    uint2 u;
    u.x = *reinterpret_cast<unsigned*>(&h01);
    u.y = *reinterpret_cast<unsigned*>(&h23);
    reinterpret_cast<uint2*>(g_xw4)[(size_t)r * 32 + lane] = u;
}

// ---------------------------------------------------------------------------
// 7) stage 2 gather + ReLU, half-warp per row:
//    lane(0..15) loads uint4 = 8 fp16 dims; 16 lanes x 16B = 256B row.
// ---------------------------------------------------------------------------
__global__ void agg_gather_kernel(float* __restrict__ out) {
    int gtid = blockIdx.x * blockDim.x + threadIdx.x;
    int r    = gtid >> 4;        // half-warp per row
    int lane = gtid & 15;
    if (r >= N_NODES) return;

    int s = g_off_a[r];
    int e = g_cur_a[r];

    float a0 = 0.f, a1 = 0.f, a2 = 0.f, a3 = 0.f;
    float a4 = 0.f, a5 = 0.f, a6 = 0.f, a7 = 0.f;
#pragma unroll 2
    for (int j = s; j < e; j++) {
        int2 p = __ldg(g_pair_a + j);
        float v = __int_as_float(p.y);
        uint4 u = __ldg(g_xw4 + (size_t)p.x * 16 + lane);
        __half2 h0 = *reinterpret_cast<__half2*>(&u.x);
        __half2 h1 = *reinterpret_cast<__half2*>(&u.y);
        __half2 h2 = *reinterpret_cast<__half2*>(&u.z);
        __half2 h3 = *reinterpret_cast<__half2*>(&u.w);
        float2 f0 = __half22float2(h0);
        float2 f1 = __half22float2(h1);
        float2 f2 = __half22float2(h2);
        float2 f3 = __half22float2(h3);
        a0 = fmaf(v, f0.x, a0);  a1 = fmaf(v, f0.y, a1);
        a2 = fmaf(v, f1.x, a2);  a3 = fmaf(v, f1.y, a3);
        a4 = fmaf(v, f2.x, a4);  a5 = fmaf(v, f2.y, a5);
        a6 = fmaf(v, f3.x, a6);  a7 = fmaf(v, f3.y, a7);
    }
    float4 o0 = make_float4(fmaxf(a0, 0.f), fmaxf(a1, 0.f),
                            fmaxf(a2, 0.f), fmaxf(a3, 0.f));
    float4 o1 = make_float4(fmaxf(a4, 0.f), fmaxf(a5, 0.f),
                            fmaxf(a6, 0.f), fmaxf(a7, 0.f));
    float4* orow = reinterpret_cast<float4*>(out + (size_t)r * OUT_DIM);
    orow[lane * 2]     = o0;
    orow[lane * 2 + 1] = o1;
}

// ---------------------------------------------------------------------------
// metadata order: feat_rows, feat_cols, feat_vals, adj_rows, adj_cols,
//                 adj_vals, W, n_nodes
// ---------------------------------------------------------------------------
extern "C" void kernel_launch(void* const* d_in, const int* in_sizes, int n_in,
                              void* d_out, int out_size) {
    const int*   feat_rows = (const int*)d_in[0];
    const int*   feat_cols = (const int*)d_in[1];
    const float* feat_vals = (const float*)d_in[2];
    const int*   adj_rows  = (const int*)d_in[3];
    const int*   adj_cols  = (const int*)d_in[4];
    const float* adj_vals  = (const float*)d_in[5];
    const float* W         = (const float*)d_in[6];
    float* out = (float*)d_out;

    zero_cnt_kernel<<<(N_NODES + 255) / 256, 256>>>();
    hist_kernel<<<(NNZ_X + 255) / 256, 256>>>(feat_rows, adj_rows);

    dim3 sg(SCAN_NBLK, 2);
    block_sum_kernel<<<sg, 256>>>();
    scan_bsum_kernel<<<1, 128>>>();
    scan_add_kernel<<<sg, 256>>>();

    dim3 sc((NNZ_X + 255) / 256, 2);
    scatter_pairs_kernel<<<sc, 256>>>(feat_rows, feat_cols, feat_vals,
                                      adj_rows, adj_cols, adj_vals);

    xw_gather_kernel<<<(N_NODES * 32 + 255) / 256, 256>>>(W);
    agg_gather_kernel<<<(N_NODES * 16 + 255) / 256, 256>>>(out);
}

// round 7
// speedup vs baseline: 2.6573x; 1.0544x over previous
#include <cuda_runtime.h>
#include <cuda_fp16.h>

#define N_NODES 100000
#define N_FEAT  256
#define OUT_DIM 128
#define NNZ_X   1600000
#define NNZ_A   1600000

#define SCAN_CHUNK 2048          // 256 threads x 8 elems
#define SCAN_NBLK  ((N_NODES + SCAN_CHUNK - 1) / SCAN_CHUNK)   // 49

// ---------------- device scratch (device-code references only) ----------------
__device__ uint4  g_xw4[(size_t)N_NODES * 16];   // xw fp16: row = 256 B = 16 uint4
__device__ __half g_W16[N_FEAT * OUT_DIM];       // fp16 copy of W (64 KB)

__device__ int   g_cnt_f[N_NODES];
__device__ int   g_cnt_a[N_NODES];
__device__ int   g_off_f[N_NODES];
__device__ int   g_off_a[N_NODES];
__device__ int   g_cur_f[N_NODES];
__device__ int   g_cur_a[N_NODES];

// decoupled-lookback state, PACKED: high32 = flag (0=invalid,1=agg,2=inclusive),
// low32 = value. Single 64-bit atomic publish -> no torn (flag,value) reads.
__device__ unsigned long long g_scan_pack[2][SCAN_NBLK];

// packed (col, val-bits) pairs, row-sorted
__device__ int2  g_pair_f[NNZ_X];
__device__ int2  g_pair_a[NNZ_A];

// ---------------------------------------------------------------------------
// 0) zero histograms + reset scan state + convert W to fp16
// ---------------------------------------------------------------------------
__global__ void init_kernel(const float* __restrict__ W) {
    int i = blockIdx.x * blockDim.x + threadIdx.x;
    if (i < N_NODES) { g_cnt_f[i] = 0; g_cnt_a[i] = 0; }
    if (i < 2 * SCAN_NBLK) {
        g_scan_pack[i / SCAN_NBLK][i % SCAN_NBLK] = 0ULL;
    }
    if (i < N_FEAT * OUT_DIM) {
        g_W16[i] = __float2half_rn(__ldg(W + i));
    }
}

// ---------------------------------------------------------------------------
// 1) histogram both row arrays (fused)
// ---------------------------------------------------------------------------
__global__ void hist_kernel(const int* __restrict__ rows_f,
                            const int* __restrict__ rows_a) {
    int i = blockIdx.x * blockDim.x + threadIdx.x;
    if (i < NNZ_X) atomicAdd(&g_cnt_f[__ldg(rows_f + i)], 1);
    if (i < NNZ_A) atomicAdd(&g_cnt_a[__ldg(rows_a + i)], 1);
}

// ---------------------------------------------------------------------------
// 2) single-pass exclusive scan (decoupled lookback, packed flag|value).
//    grid=(SCAN_NBLK, 2). 98 blocks <= 148 SMs -> all resident, spin is safe.
// ---------------------------------------------------------------------------
__global__ void scan_kernel() {
    __shared__ int s[256];
    __shared__ int s_excl;
    int arr = blockIdx.y;
    const int* cnt = (arr == 0) ? g_cnt_f : g_cnt_a;
    int* off = (arr == 0) ? g_off_f : g_off_a;
    int* cur = (arr == 0) ? g_cur_f : g_cur_a;

    int t = threadIdx.x;
    int bid = blockIdx.x;
    int base = bid * SCAN_CHUNK + t * 8;

    int local[8];
    int sum = 0;
#pragma unroll
    for (int k = 0; k < 8; k++) {
        int idx = base + k;
        local[k] = (idx < N_NODES) ? cnt[idx] : 0;
        sum += local[k];
    }
    s[t] = sum;
    __syncthreads();
    for (int d = 1; d < 256; d <<= 1) {
        int v = (t >= d) ? s[t - d] : 0;
        __syncthreads();
        s[t] += v;
        __syncthreads();
    }
    int block_total = s[255];

    if (t == 0) {
        if (bid == 0) {
            atomicExch(&g_scan_pack[arr][0],
                       (2ULL << 32) | (unsigned)block_total);
            s_excl = 0;
        } else {
            atomicExch(&g_scan_pack[arr][bid],
                       (1ULL << 32) | (unsigned)block_total);
            int running = 0;
            for (int p = bid - 1; p >= 0; p--) {
                unsigned long long pk;
                do { pk = atomicAdd(&g_scan_pack[arr][p], 0ULL); }
                while ((pk >> 32) == 0ULL);
                running += (int)(unsigned)pk;
                if ((pk >> 32) == 2ULL) break;
            }
            atomicExch(&g_scan_pack[arr][bid],
                       (2ULL << 32) | (unsigned)(running + block_total));
            s_excl = running;
        }
    }
    __syncthreads();
    int excl_blk = s_excl;

    int excl_thr = (t == 0) ? 0 : s[t - 1];
    int run = excl_blk + excl_thr;
#pragma unroll
    for (int k = 0; k < 8; k++) {
        int idx = base + k;
        if (idx < N_NODES) { off[idx] = run; cur[idx] = run; run += local[k]; }
    }
}

// ---------------------------------------------------------------------------
// 3) scatter packed (col,val) pairs into row-sorted order (atomic cursors).
// ---------------------------------------------------------------------------
__global__ void scatter_pairs_kernel(const int* __restrict__ rows_f,
                                     const int* __restrict__ cols_f,
                                     const float* __restrict__ vals_f,
                                     const int* __restrict__ rows_a,
                                     const int* __restrict__ cols_a,
                                     const float* __restrict__ vals_a) {
    int i = blockIdx.x * blockDim.x + threadIdx.x;
    if (blockIdx.y == 0) {
        if (i >= NNZ_X) return;
        int r = __ldg(rows_f + i);
        int pos = atomicAdd(&g_cur_f[r], 1);
        int2 p;
        p.x = __ldg(cols_f + i);
        p.y = __float_as_int(__ldg(vals_f + i));
        g_pair_f[pos] = p;
    } else {
        if (i >= NNZ_A) return;
        int r = __ldg(rows_a + i);
        int pos = atomicAdd(&g_cur_a[r], 1);
        int2 p;
        p.x = __ldg(cols_a + i);
        p.y = __float_as_int(__ldg(vals_a + i));
        g_pair_a[pos] = p;
    }
}

// ---------------------------------------------------------------------------
// 4) stage 1 gather: xw[r,:] = sum_j val[j] * W16[col[j],:]
//    half-warp per row; lane(0..15) owns 8 dims, loads uint4 = 8 fp16 of W.
//    fp32 accumulate, one fp16 round at the end.
// ---------------------------------------------------------------------------
__global__ void xw_gather_kernel() {
    int gtid = blockIdx.x * blockDim.x + threadIdx.x;
    int r    = gtid >> 4;
    int lane = gtid & 15;
    if (r >= N_NODES) return;

    int s = g_off_f[r];
    int e = g_cur_f[r];

    const uint4* W4 = reinterpret_cast<const uint4*>(g_W16);
    float a0 = 0.f, a1 = 0.f, a2 = 0.f, a3 = 0.f;
    float a4 = 0.f, a5 = 0.f, a6 = 0.f, a7 = 0.f;
#pragma unroll 2
    for (int j = s; j < e; j++) {
        int2 p = __ldg(g_pair_f + j);
        float v = __int_as_float(p.y);
        uint4 u = __ldg(W4 + (size_t)p.x * 16 + lane);
        float2 f0 = __half22float2(*reinterpret_cast<__half2*>(&u.x));
        float2 f1 = __half22float2(*reinterpret_cast<__half2*>(&u.y));
        float2 f2 = __half22float2(*reinterpret_cast<__half2*>(&u.z));
        float2 f3 = __half22float2(*reinterpret_cast<__half2*>(&u.w));
        a0 = fmaf(v, f0.x, a0);  a1 = fmaf(v, f0.y, a1);
        a2 = fmaf(v, f1.x, a2);  a3 = fmaf(v, f1.y, a3);
        a4 = fmaf(v, f2.x, a4);  a5 = fmaf(v, f2.y, a5);
        a6 = fmaf(v, f3.x, a6);  a7 = fmaf(v, f3.y, a7);
    }
    __half2 h0 = __floats2half2_rn(a0, a1);
    __half2 h1 = __floats2half2_rn(a2, a3);
    __half2 h2 = __floats2half2_rn(a4, a5);
    __half2 h3 = __floats2half2_rn(a6, a7);
    uint4 u;
    u.x = *reinterpret_cast<unsigned*>(&h0);
    u.y = *reinterpret_cast<unsigned*>(&h1);
    u.z = *reinterpret_cast<unsigned*>(&h2);
    u.w = *reinterpret_cast<unsigned*>(&h3);
    g_xw4[(size_t)r * 16 + lane] = u;
}

// ---------------------------------------------------------------------------
// 5) stage 2 gather + ReLU, half-warp per row (uint4 fp16 loads from L2).
// ---------------------------------------------------------------------------
__global__ void agg_gather_kernel(float* __restrict__ out) {
    int gtid = blockIdx.x * blockDim.x + threadIdx.x;
    int r    = gtid >> 4;
    int lane = gtid & 15;
    if (r >= N_NODES) return;

    int s = g_off_a[r];
    int e = g_cur_a[r];

    float a0 = 0.f, a1 = 0.f, a2 = 0.f, a3 = 0.f;
    float a4 = 0.f, a5 = 0.f, a6 = 0.f, a7 = 0.f;
#pragma unroll 2
    for (int j = s; j < e; j++) {
        int2 p = __ldg(g_pair_a + j);
        float v = __int_as_float(p.y);
        uint4 u = __ldg(g_xw4 + (size_t)p.x * 16 + lane);
        float2 f0 = __half22float2(*reinterpret_cast<__half2*>(&u.x));
        float2 f1 = __half22float2(*reinterpret_cast<__half2*>(&u.y));
        float2 f2 = __half22float2(*reinterpret_cast<__half2*>(&u.z));
        float2 f3 = __half22float2(*reinterpret_cast<__half2*>(&u.w));
        a0 = fmaf(v, f0.x, a0);  a1 = fmaf(v, f0.y, a1);
        a2 = fmaf(v, f1.x, a2);  a3 = fmaf(v, f1.y, a3);
        a4 = fmaf(v, f2.x, a4);  a5 = fmaf(v, f2.y, a5);
        a6 = fmaf(v, f3.x, a6);  a7 = fmaf(v, f3.y, a7);
    }
    float4 o0 = make_float4(fmaxf(a0, 0.f), fmaxf(a1, 0.f),
                            fmaxf(a2, 0.f), fmaxf(a3, 0.f));
    float4 o1 = make_float4(fmaxf(a4, 0.f), fmaxf(a5, 0.f),
                            fmaxf(a6, 0.f), fmaxf(a7, 0.f));
    float4* orow = reinterpret_cast<float4*>(out + (size_t)r * OUT_DIM);
    orow[lane * 2]     = o0;
    orow[lane * 2 + 1] = o1;
}

// ---------------------------------------------------------------------------
// metadata order: feat_rows, feat_cols, feat_vals, adj_rows, adj_cols,
//                 adj_vals, W, n_nodes
// ---------------------------------------------------------------------------
extern "C" void kernel_launch(void* const* d_in, const int* in_sizes, int n_in,
                              void* d_out, int out_size) {
    const int*   feat_rows = (const int*)d_in[0];
    const int*   feat_cols = (const int*)d_in[1];
    const float* feat_vals = (const float*)d_in[2];
    const int*   adj_rows  = (const int*)d_in[3];
    const int*   adj_cols  = (const int*)d_in[4];
    const float* adj_vals  = (const float*)d_in[5];
    const float* W         = (const float*)d_in[6];
    float* out = (float*)d_out;

    init_kernel<<<(N_NODES + 255) / 256, 256>>>(W);
    hist_kernel<<<(NNZ_X + 255) / 256, 256>>>(feat_rows, adj_rows);

    dim3 sg(SCAN_NBLK, 2);
    scan_kernel<<<sg, 256>>>();

    dim3 sc((NNZ_X + 255) / 256, 2);
    scatter_pairs_kernel<<<sc, 256>>>(feat_rows, feat_cols, feat_vals,
                                      adj_rows, adj_cols, adj_vals);

    xw_gather_kernel<<<(N_NODES * 16 + 255) / 256, 256>>>();
    agg_gather_kernel<<<(N_NODES * 16 + 255) / 256, 256>>>(out);
}